// round 11
// baseline (speedup 1.0000x reference)
#include <cuda_runtime.h>
#include <cstdint>

#define B_  8
#define N_  256
#define DN  64
#define DE  32
#define DC  64
#define DO_ 60
#define CPB  37           // CTAs per batch
#define GRID (8*CPB)      // 296

__device__ __align__(16) float g_pr [B_*N_*DC];
__device__ __align__(16) float g_psb[B_*N_*DC];

// ---------------------------------------------------------------------------
// Kernel A: per-node precompute.
// ---------------------------------------------------------------------------
__global__ void precompute_kernel(const float* __restrict__ node,
                                  const float* __restrict__ W_e,
                                  const float* __restrict__ b_e,
                                  const float* __restrict__ W_n,
                                  const float* __restrict__ b_n,
                                  float* __restrict__ out) {
    __shared__ float nrow[DN];
    const int bn = blockIdx.x;
    const int c  = threadIdx.x;              // 0..63
    nrow[c] = node[bn*DN + c];
    __syncthreads();

    float accR = 0.f, accS = 0.f, accO = 0.f;
    #pragma unroll 8
    for (int k = 0; k < DN; k++) {
        float nv = nrow[k];
        accR = fmaf(nv, W_e[(DE      + k)*DC + c], accR);
        accS = fmaf(nv, W_e[(DE + DN + k)*DC + c], accS);
        if (c < DO_) accO = fmaf(nv, W_n[k*DO_ + c], accO);
    }
    g_pr [bn*DC + c] = accR;
    g_psb[bn*DC + c] = accS + b_e[c];
    if (c < DO_) out[bn*DO_ + c] = accO + b_n[c];
}

// ---------------------------------------------------------------------------
// tf32 / math / async helpers
// ---------------------------------------------------------------------------
__device__ __forceinline__ uint32_t tf32r(float f) {
    uint32_t u;
    asm("cvt.rna.tf32.f32 %0, %1;" : "=r"(u) : "f"(f));
    return u;
}
__device__ __forceinline__ void mma_1688(float c[4],
                                         const uint32_t a[4],
                                         uint32_t b0, uint32_t b1) {
    asm volatile("mma.sync.aligned.m16n8k8.row.col.f32.tf32.tf32.f32 "
                 "{%0,%1,%2,%3}, {%4,%5,%6,%7}, {%8,%9}, {%0,%1,%2,%3};"
                 : "+f"(c[0]), "+f"(c[1]), "+f"(c[2]), "+f"(c[3])
                 : "r"(a[0]), "r"(a[1]), "r"(a[2]), "r"(a[3]), "r"(b0), "r"(b1));
}
__device__ __forceinline__ float lrelu_m(float x, float a1, float a001) {
    return x * ((x >= 0.f) ? a1 : a001);
}
__device__ __forceinline__ void cp16(uint32_t smem_addr, const void* gptr) {
    asm volatile("cp.async.cg.shared.global [%0], [%1], 16;"
                 :: "r"(smem_addr), "l"(gptr));
}

#define ESTRIDE 36   // bank = 4g + t  -> conflict-free A-frag loads
#define WSTRIDE 72   // bank = 8t + g  -> conflict-free B-frag loads

// Dynamic smem layout (bytes)
#define OFF_E0   0u          // half-tile buf0: 128*36*4 = 18432
#define OFF_E1   18432u      // half-tile buf1: 18432
#define OFF_PSB  36864u      // psbT swizzled [64][256] f32 = 65536
#define OFF_W    102400u     // 32*72*4 = 9216
#define OFF_RED  111616u     // 8*64 f32 = 2048
#define OFF_AGG  113664u     // 64 f32 = 256
#define SMEM_DYN 113920u     // <= 116224 -> 2 CTAs/SM

// psbT word index: c*256 + (s ^ (8*((c>>1)&3)))  (conflict-free reads)
__device__ __forceinline__ int psb_idx(int c, int s) {
    return c*256 + (s ^ (8*((c >> 1) & 3)));
}

// ---------------------------------------------------------------------------
// Kernel B: batch-locked persistent CTAs. CTA (batch, cb) handles contiguous
// receivers [cb*256/37, (cb+1)*256/37) of one batch. psbT staged once per CTA.
// E pipeline at half-receiver (128-sender) granularity, double-buffered.
// Warp w = senders [16w,16w+16) of the current half (one m16 tile).
// ---------------------------------------------------------------------------
__global__ void __launch_bounds__(256, 2) edge_kernel(
    const float* __restrict__ edge_attr,
    const float* __restrict__ adj,
    const float* __restrict__ W_e,
    const float* __restrict__ W_n,
    float* __restrict__ out) {

    extern __shared__ __align__(16) unsigned char dynsm[];
    float*    psbS = (float*)   (dynsm + OFF_PSB);
    uint32_t* Wsm  = (uint32_t*)(dynsm + OFF_W);
    float*    red  = (float*)   (dynsm + OFF_RED);
    float*    agg  = (float*)   (dynsm + OFF_AGG);
    const uint32_t esm0 = (uint32_t)__cvta_generic_to_shared(dynsm);

    const int tid  = threadIdx.x;
    const int bx   = blockIdx.x;
    const int wid  = tid >> 5;
    const int lane = tid & 31;
    const int g    = lane >> 2;            // 0..7
    const int t    = lane & 3;             // 0..3

    const int batch = bx / CPB;
    const int cb    = bx % CPB;
    const int rs    = (cb * N_) / CPB;
    const int re    = ((cb + 1) * N_) / CPB;
    const int nr    = re - rs;             // 6 or 7
    const int bn0   = batch * N_ + rs;

    // --- fire first half-load (receiver bn0, half 0) into buf0 ---
    {
        const float4* esrc = (const float4*)edge_attr + (size_t)bn0 * 2048;
        #pragma unroll
        for (int i = 0; i < 4; i++) {
            int idx = tid + i*256;                 // 0..1023 float4
            int row = idx >> 3, q = idx & 7;
            cp16(esm0 + (uint32_t)(row*ESTRIDE + q*4)*4u, esrc + idx);
        }
        asm volatile("cp.async.commit_group;");
    }

    // --- stage W (under load-0 latency) ---
    #pragma unroll
    for (int i = 0; i < 8; i++) {
        int idx = tid + i*256;
        Wsm[(idx >> 6)*WSTRIDE + (idx & 63)] = tf32r(W_e[idx]);
    }
    // --- stage psbT for this batch (once), swizzled transpose ---
    {
        const float4* psrc = (const float4*)g_psb + (size_t)batch * 4096;
        #pragma unroll
        for (int i = 0; i < 16; i++) {
            int idx4 = tid + i*256;                // 0..4095
            float4 v = psrc[idx4];
            int s = idx4 >> 4;
            int c = (idx4 & 15) * 4;
            psbS[psb_idx(c    , s)] = v.x;
            psbS[psb_idx(c + 1, s)] = v.y;
            psbS[psb_idx(c + 2, s)] = v.z;
            psbS[psb_idx(c + 3, s)] = v.w;
        }
    }

    const int swz = 8*t;                   // read-side swizzle (constant/thread)

    for (int ri = 0; ri < nr; ri++) {
        const int bn = bn0 + ri;
        const float* prp = g_pr + (size_t)bn*DC + 2*t;

        float ux[8], uy[8];
        #pragma unroll
        for (int nt = 0; nt < 8; nt++) { ux[nt] = 0.f; uy[nt] = 0.f; }

        #pragma unroll
        for (int h = 0; h < 2; h++) {
            const int m = 2*ri + h;
            // --- issue next half-load into the other buffer ---
            if (m + 1 < 2*nr) {
                const int rn = (m + 1) >> 1, hn = (m + 1) & 1;
                const float4* esrc = (const float4*)edge_attr
                                   + (size_t)(bn0 + rn) * 2048 + hn * 1024;
                const uint32_t eb = esm0 + (uint32_t)((m + 1) & 1) * OFF_E1;
                #pragma unroll
                for (int i = 0; i < 4; i++) {
                    int idx = tid + i*256;
                    int row = idx >> 3, q = idx & 7;
                    cp16(eb + (uint32_t)(row*ESTRIDE + q*4)*4u, esrc + idx);
                }
                asm volatile("cp.async.commit_group;");
                asm volatile("cp.async.wait_group 1;" ::: "memory");
            } else {
                asm volatile("cp.async.wait_group 0;" ::: "memory");
            }

            // adj for this half's two rows (issue before barrier)
            const int sg_lo = h*128 + 16*wid + g;
            const float a_lo = __ldg(adj + (size_t)bn*N_ + sg_lo);
            const float a_hi = __ldg(adj + (size_t)bn*N_ + sg_lo + 8);
            const float a_lo1 = 0.01f * a_lo, a_hi1 = 0.01f * a_hi;

            __syncthreads();

            // --- A fragments from current half buffer ---
            const uint32_t* Eb = (const uint32_t*)(dynsm + (m & 1)*OFF_E1);
            const int lo = 16*wid + g, hi = lo + 8;
            uint32_t afr[4][4];
            #pragma unroll
            for (int ks = 0; ks < 4; ks++) {
                const int k0 = 8*ks + t;
                afr[ks][0] = tf32r(__uint_as_float(Eb[lo*ESTRIDE + k0    ]));
                afr[ks][1] = tf32r(__uint_as_float(Eb[hi*ESTRIDE + k0    ]));
                afr[ks][2] = tf32r(__uint_as_float(Eb[lo*ESTRIDE + k0 + 4]));
                afr[ks][3] = tf32r(__uint_as_float(Eb[hi*ESTRIDE + k0 + 4]));
            }

            const int slo = sg_lo ^ swz;
            const int shi = (sg_lo + 8) ^ swz;

            #pragma unroll
            for (int nt = 0; nt < 8; nt += 2) {
                const int cA = 8*nt + 2*t, cB = cA + 8;
                const float2 prA = *(const float2*)(prp + 8*nt);
                const float2 prB = *(const float2*)(prp + 8*nt + 8);

                float acc0[4] = { psbS[cA*256 + slo] + prA.x,
                                  psbS[(cA+1)*256 + slo] + prA.y,
                                  psbS[cA*256 + shi] + prA.x,
                                  psbS[(cA+1)*256 + shi] + prA.y };
                float acc1[4] = { psbS[cB*256 + slo] + prB.x,
                                  psbS[(cB+1)*256 + slo] + prB.y,
                                  psbS[cB*256 + shi] + prB.x,
                                  psbS[(cB+1)*256 + shi] + prB.y };

                #pragma unroll
                for (int ks = 0; ks < 4; ks++) {
                    uint32_t b0a = Wsm[(8*ks + t    )*WSTRIDE + 8*nt + g];
                    uint32_t b1a = Wsm[(8*ks + t + 4)*WSTRIDE + 8*nt + g];
                    uint32_t b0b = Wsm[(8*ks + t    )*WSTRIDE + 8*nt + 8 + g];
                    uint32_t b1b = Wsm[(8*ks + t + 4)*WSTRIDE + 8*nt + 8 + g];
                    mma_1688(acc0, afr[ks], b0a, b1a);
                    mma_1688(acc1, afr[ks], b0b, b1b);
                }

                ux[nt]   += lrelu_m(acc0[0], a_lo, a_lo1) + lrelu_m(acc0[2], a_hi, a_hi1);
                uy[nt]   += lrelu_m(acc0[1], a_lo, a_lo1) + lrelu_m(acc0[3], a_hi, a_hi1);
                ux[nt+1] += lrelu_m(acc1[0], a_lo, a_lo1) + lrelu_m(acc1[2], a_hi, a_hi1);
                uy[nt+1] += lrelu_m(acc1[1], a_lo, a_lo1) + lrelu_m(acc1[3], a_hi, a_hi1);
            }
        } // halves

        // --- cross-lane butterfly over the 8 groups ---
        #pragma unroll
        for (int nt = 0; nt < 8; nt++) {
            #pragma unroll
            for (int st = 4; st <= 16; st <<= 1) {
                ux[nt] += __shfl_xor_sync(0xffffffffu, ux[nt], st);
                uy[nt] += __shfl_xor_sync(0xffffffffu, uy[nt], st);
            }
        }
        if (lane < 4) {
            #pragma unroll
            for (int nt = 0; nt < 8; nt++)
                *(float2*)&red[wid*DC + 8*nt + 2*t] = make_float2(ux[nt], uy[nt]);
        }
        __syncthreads();

        if (tid < DC) {
            float a = 0.f;
            #pragma unroll
            for (int w = 0; w < 8; w++) a += red[w*DC + tid];
            agg[tid] = a;
        }
        __syncthreads();

        if (tid < DO_) {
            float sum = out[(size_t)bn*DO_ + tid];
            #pragma unroll 8
            for (int cc = 0; cc < DC; cc++)
                sum = fmaf(agg[cc], W_n[(DN + cc)*DO_ + tid], sum);
            out[(size_t)bn*DO_ + tid] = sum;
        }
    } // receivers
}

// ---------------------------------------------------------------------------
extern "C" void kernel_launch(void* const* d_in, const int* in_sizes, int n_in,
                              void* d_out, int out_size) {
    const float* node = (const float*)d_in[0];
    const float* edge = (const float*)d_in[1];
    const float* adjp = (const float*)d_in[2];
    const float* W_e  = (const float*)d_in[3];
    const float* b_e  = (const float*)d_in[4];
    const float* W_n  = (const float*)d_in[5];
    const float* b_n  = (const float*)d_in[6];
    float* out = (float*)d_out;

    cudaFuncSetAttribute(edge_kernel, cudaFuncAttributeMaxDynamicSharedMemorySize, SMEM_DYN);

    precompute_kernel<<<B_*N_, 64>>>(node, W_e, b_e, W_n, b_n, out);
    edge_kernel<<<GRID, 256, SMEM_DYN>>>(edge, adjp, W_e, W_n, out);
}

// round 12
// speedup vs baseline: 1.1243x; 1.1243x over previous
#include <cuda_runtime.h>
#include <cstdint>

#define B_  8
#define N_  256
#define DN  64
#define DE  32
#define DC  64
#define DO_ 60
#define CPB  37           // CTAs per batch
#define GRID (8*CPB)      // 296

__device__ __align__(16) float g_pr [B_*N_*DC];
__device__ __align__(16) float g_psb[B_*N_*DC];

// ---------------------------------------------------------------------------
// Kernel A: per-node precompute.
// ---------------------------------------------------------------------------
__global__ void precompute_kernel(const float* __restrict__ node,
                                  const float* __restrict__ W_e,
                                  const float* __restrict__ b_e,
                                  const float* __restrict__ W_n,
                                  const float* __restrict__ b_n,
                                  float* __restrict__ out) {
    __shared__ float nrow[DN];
    const int bn = blockIdx.x;
    const int c  = threadIdx.x;              // 0..63
    nrow[c] = node[bn*DN + c];
    __syncthreads();

    float accR = 0.f, accS = 0.f, accO = 0.f;
    #pragma unroll 8
    for (int k = 0; k < DN; k++) {
        float nv = nrow[k];
        accR = fmaf(nv, W_e[(DE      + k)*DC + c], accR);
        accS = fmaf(nv, W_e[(DE + DN + k)*DC + c], accS);
        if (c < DO_) accO = fmaf(nv, W_n[k*DO_ + c], accO);
    }
    g_pr [bn*DC + c] = accR;
    g_psb[bn*DC + c] = accS + b_e[c];
    if (c < DO_) out[bn*DO_ + c] = accO + b_n[c];
}

// ---------------------------------------------------------------------------
// tf32 / math / async helpers
// ---------------------------------------------------------------------------
__device__ __forceinline__ uint32_t tf32r(float f) {
    uint32_t u;
    asm("cvt.rna.tf32.f32 %0, %1;" : "=r"(u) : "f"(f));
    return u;
}
__device__ __forceinline__ void mma_1688(float c[4],
                                         const uint32_t a[4],
                                         uint32_t b0, uint32_t b1) {
    asm volatile("mma.sync.aligned.m16n8k8.row.col.f32.tf32.tf32.f32 "
                 "{%0,%1,%2,%3}, {%4,%5,%6,%7}, {%8,%9}, {%0,%1,%2,%3};"
                 : "+f"(c[0]), "+f"(c[1]), "+f"(c[2]), "+f"(c[3])
                 : "r"(a[0]), "r"(a[1]), "r"(a[2]), "r"(a[3]), "r"(b0), "r"(b1));
}
__device__ __forceinline__ float lrelu_m(float x, float a1, float a001) {
    return x * ((x >= 0.f) ? a1 : a001);
}
__device__ __forceinline__ void cp16(uint32_t smem_addr, const void* gptr) {
    asm volatile("cp.async.cg.shared.global [%0], [%1], 16;"
                 :: "r"(smem_addr), "l"(gptr));
}

#define ESTRIDE 36   // bank = 4g + t  -> conflict-free A-frag loads

// Dynamic smem layout (bytes)
#define OFF_E0   0u          // half-tile buf0: 128*36*4 = 18432
#define OFF_E1   18432u      // half-tile buf1: 18432
#define OFF_PSB  36864u      // psbT swizzled [64][256] f32 = 65536
#define OFF_RED  102400u     // 8*64 f32 = 2048
#define OFF_AGG  104448u     // 64 f32 = 256
#define SMEM_DYN 104704u     // -> 2 CTAs/SM

// psbT word index: c*256 + (s ^ (8*((c>>1)&3)))  (conflict-free reads)
__device__ __forceinline__ int psb_idx(int c, int s) {
    return c*256 + (s ^ (8*((c >> 1) & 3)));
}

// ---------------------------------------------------------------------------
// Kernel B: batch-locked persistent CTAs; psbT staged once; W (B-fragments)
// fully REGISTER-RESIDENT (loaded once from gmem); E pipeline at
// half-receiver granularity with WARP-PRIVATE cp.async (each warp loads
// exactly the 16 rows it consumes) -> no CTA barrier in the half loop,
// only wait_group + __syncwarp. Reduction barriers only per receiver.
// ---------------------------------------------------------------------------
__global__ void __launch_bounds__(256, 2) edge_kernel(
    const float* __restrict__ edge_attr,
    const float* __restrict__ adj,
    const float* __restrict__ W_e,
    const float* __restrict__ W_n,
    float* __restrict__ out) {

    extern __shared__ __align__(16) unsigned char dynsm[];
    float* psbS = (float*)(dynsm + OFF_PSB);
    float* red  = (float*)(dynsm + OFF_RED);
    float* agg  = (float*)(dynsm + OFF_AGG);
    const uint32_t esm0 = (uint32_t)__cvta_generic_to_shared(dynsm);

    const int tid  = threadIdx.x;
    const int bx   = blockIdx.x;
    const int wid  = tid >> 5;             // 0..7
    const int lane = tid & 31;
    const int g    = lane >> 2;            // 0..7
    const int t    = lane & 3;             // 0..3

    const int batch = bx / CPB;
    const int cb    = bx % CPB;
    const int rs    = (cb * N_) / CPB;
    const int re    = ((cb + 1) * N_) / CPB;
    const int nr    = re - rs;             // 6 or 7
    const int bn0   = batch * N_ + rs;

    // warp-private E row mapping: lane l loads rows 16w + (l>>3) + 4i, chunk l&7
    const int erow = 16*wid + (lane >> 3);
    const int eq   = lane & 7;

    // --- fire first half-load (receiver bn0, half 0) into buf0 ---
    {
        const float* esrc = edge_attr + (size_t)bn0 * (N_*DE);
        #pragma unroll
        for (int i = 0; i < 4; i++) {
            int r = erow + 4*i;
            cp16(esm0 + (uint32_t)(r*ESTRIDE + eq*4)*4u, esrc + r*DE + eq*4);
        }
        asm volatile("cp.async.commit_group;");
    }

    // --- B-fragments register-resident (one-time gmem loads, L2-shared) ---
    uint32_t bfr[8][4][2];
    #pragma unroll
    for (int nt = 0; nt < 8; nt++)
        #pragma unroll
        for (int ks = 0; ks < 4; ks++) {
            bfr[nt][ks][0] = tf32r(__ldg(W_e + (8*ks + t    )*DC + 8*nt + g));
            bfr[nt][ks][1] = tf32r(__ldg(W_e + (8*ks + t + 4)*DC + 8*nt + g));
        }

    // --- stage psbT for this batch (once), swizzled transpose ---
    {
        const float4* psrc = (const float4*)g_psb + (size_t)batch * 4096;
        #pragma unroll
        for (int i = 0; i < 16; i++) {
            int idx4 = tid + i*256;                // 0..4095
            float4 v = psrc[idx4];
            int s = idx4 >> 4;
            int c = (idx4 & 15) * 4;
            psbS[psb_idx(c    , s)] = v.x;
            psbS[psb_idx(c + 1, s)] = v.y;
            psbS[psb_idx(c + 2, s)] = v.z;
            psbS[psb_idx(c + 3, s)] = v.w;
        }
    }
    __syncthreads();                        // psbS visible to all warps

    const int swz = 8*t;

    for (int ri = 0; ri < nr; ri++) {
        const int bn = bn0 + ri;
        const float* prp = g_pr + (size_t)bn*DC + 2*t;

        // prefetch out RMW value (used ~2K cycles later)
        float outv = (tid < DO_) ? out[(size_t)bn*DO_ + tid] : 0.f;

        float ux[8], uy[8];
        #pragma unroll
        for (int nt = 0; nt < 8; nt++) { ux[nt] = 0.f; uy[nt] = 0.f; }

        #pragma unroll
        for (int h = 0; h < 2; h++) {
            const int m = 2*ri + h;

            // --- prefetch next half (warp-private rows) ---
            if (m + 1 < 2*nr) {
                const int rn = (m + 1) >> 1, hn = (m + 1) & 1;
                const float* esrc = edge_attr
                    + (size_t)(bn0 + rn) * (N_*DE) + hn * (128*DE);
                const uint32_t eb = esm0 + (uint32_t)((m + 1) & 1) * OFF_E1;
                #pragma unroll
                for (int i = 0; i < 4; i++) {
                    int r = erow + 4*i;
                    cp16(eb + (uint32_t)(r*ESTRIDE + eq*4)*4u, esrc + r*DE + eq*4);
                }
                asm volatile("cp.async.commit_group;");
                asm volatile("cp.async.wait_group 1;" ::: "memory");
            } else {
                asm volatile("cp.async.wait_group 0;" ::: "memory");
            }
            __syncwarp();                   // intra-warp visibility; no CTA barrier

            const int sg_lo = h*128 + 16*wid + g;    // global sender of row lo
            const float a_lo = __ldg(adj + (size_t)bn*N_ + sg_lo);
            const float a_hi = __ldg(adj + (size_t)bn*N_ + sg_lo + 8);
            const float a_lo1 = 0.01f * a_lo, a_hi1 = 0.01f * a_hi;

            // --- A fragments from current half buffer (own rows only) ---
            const uint32_t* Eb = (const uint32_t*)(dynsm + (m & 1)*OFF_E1);
            const int lo = 16*wid + g, hi = lo + 8;
            uint32_t afr[4][4];
            #pragma unroll
            for (int ks = 0; ks < 4; ks++) {
                const int k0 = 8*ks + t;
                afr[ks][0] = tf32r(__uint_as_float(Eb[lo*ESTRIDE + k0    ]));
                afr[ks][1] = tf32r(__uint_as_float(Eb[hi*ESTRIDE + k0    ]));
                afr[ks][2] = tf32r(__uint_as_float(Eb[lo*ESTRIDE + k0 + 4]));
                afr[ks][3] = tf32r(__uint_as_float(Eb[hi*ESTRIDE + k0 + 4]));
            }

            const int slo = sg_lo ^ swz;
            const int shi = (sg_lo + 8) ^ swz;

            #pragma unroll
            for (int nt = 0; nt < 8; nt += 2) {
                const int cA = 8*nt + 2*t, cB = cA + 8;
                const float2 prA = *(const float2*)(prp + 8*nt);
                const float2 prB = *(const float2*)(prp + 8*nt + 8);

                float acc0[4] = { psbS[cA*256 + slo] + prA.x,
                                  psbS[(cA+1)*256 + slo] + prA.y,
                                  psbS[cA*256 + shi] + prA.x,
                                  psbS[(cA+1)*256 + shi] + prA.y };
                float acc1[4] = { psbS[cB*256 + slo] + prB.x,
                                  psbS[(cB+1)*256 + slo] + prB.y,
                                  psbS[cB*256 + shi] + prB.x,
                                  psbS[(cB+1)*256 + shi] + prB.y };

                #pragma unroll
                for (int ks = 0; ks < 4; ks++) {
                    mma_1688(acc0, afr[ks], bfr[nt    ][ks][0], bfr[nt    ][ks][1]);
                    mma_1688(acc1, afr[ks], bfr[nt + 1][ks][0], bfr[nt + 1][ks][1]);
                }

                ux[nt]   += lrelu_m(acc0[0], a_lo, a_lo1) + lrelu_m(acc0[2], a_hi, a_hi1);
                uy[nt]   += lrelu_m(acc0[1], a_lo, a_lo1) + lrelu_m(acc0[3], a_hi, a_hi1);
                ux[nt+1] += lrelu_m(acc1[0], a_lo, a_lo1) + lrelu_m(acc1[2], a_hi, a_hi1);
                uy[nt+1] += lrelu_m(acc1[1], a_lo, a_lo1) + lrelu_m(acc1[3], a_hi, a_hi1);
            }
        } // halves

        // --- cross-lane butterfly over the 8 groups ---
        #pragma unroll
        for (int nt = 0; nt < 8; nt++) {
            #pragma unroll
            for (int st = 4; st <= 16; st <<= 1) {
                ux[nt] += __shfl_xor_sync(0xffffffffu, ux[nt], st);
                uy[nt] += __shfl_xor_sync(0xffffffffu, uy[nt], st);
            }
        }
        if (lane < 4) {
            #pragma unroll
            for (int nt = 0; nt < 8; nt++)
                *(float2*)&red[wid*DC + 8*nt + 2*t] = make_float2(ux[nt], uy[nt]);
        }
        __syncthreads();

        if (tid < DC) {
            float a = 0.f;
            #pragma unroll
            for (int w = 0; w < 8; w++) a += red[w*DC + tid];
            agg[tid] = a;
        }
        __syncthreads();

        if (tid < DO_) {
            float sum = outv;
            #pragma unroll 8
            for (int cc = 0; cc < DC; cc++)
                sum = fmaf(agg[cc], W_n[(DN + cc)*DO_ + tid], sum);
            out[(size_t)bn*DO_ + tid] = sum;
        }
    } // receivers
}

// ---------------------------------------------------------------------------
extern "C" void kernel_launch(void* const* d_in, const int* in_sizes, int n_in,
                              void* d_out, int out_size) {
    const float* node = (const float*)d_in[0];
    const float* edge = (const float*)d_in[1];
    const float* adjp = (const float*)d_in[2];
    const float* W_e  = (const float*)d_in[3];
    const float* b_e  = (const float*)d_in[4];
    const float* W_n  = (const float*)d_in[5];
    const float* b_n  = (const float*)d_in[6];
    float* out = (float*)d_out;

    cudaFuncSetAttribute(edge_kernel, cudaFuncAttributeMaxDynamicSharedMemorySize, SMEM_DYN);

    precompute_kernel<<<B_*N_, 64>>>(node, W_e, b_e, W_n, b_n, out);
    edge_kernel<<<GRID, 256, SMEM_DYN>>>(edge, adjp, W_e, W_n, out);
}

// round 13
// speedup vs baseline: 1.1747x; 1.0449x over previous
#include <cuda_runtime.h>
#include <cstdint>

#define B_  8
#define N_  256
#define DN  64
#define DE  32
#define DC  64
#define DO_ 60
#define CPB  37           // CTAs per batch
#define GRID (8*CPB)      // 296

__device__ __align__(16) float g_pr [B_*N_*DC];
__device__ __align__(16) float g_psb[B_*N_*DC];

// ---------------------------------------------------------------------------
// Kernel A: per-node precompute.
// ---------------------------------------------------------------------------
__global__ void precompute_kernel(const float* __restrict__ node,
                                  const float* __restrict__ W_e,
                                  const float* __restrict__ b_e,
                                  const float* __restrict__ W_n,
                                  const float* __restrict__ b_n,
                                  float* __restrict__ out) {
    __shared__ float nrow[DN];
    const int bn = blockIdx.x;
    const int c  = threadIdx.x;              // 0..63
    nrow[c] = node[bn*DN + c];
    __syncthreads();

    float accR = 0.f, accS = 0.f, accO = 0.f;
    #pragma unroll 8
    for (int k = 0; k < DN; k++) {
        float nv = nrow[k];
        accR = fmaf(nv, W_e[(DE      + k)*DC + c], accR);
        accS = fmaf(nv, W_e[(DE + DN + k)*DC + c], accS);
        if (c < DO_) accO = fmaf(nv, W_n[k*DO_ + c], accO);
    }
    g_pr [bn*DC + c] = accR;
    g_psb[bn*DC + c] = accS + b_e[c];
    if (c < DO_) out[bn*DO_ + c] = accO + b_n[c];
}

// ---------------------------------------------------------------------------
// tf32 / math / async helpers
// ---------------------------------------------------------------------------
__device__ __forceinline__ uint32_t tf32r(float f) {
    uint32_t u;
    asm("cvt.rna.tf32.f32 %0, %1;" : "=r"(u) : "f"(f));
    return u;
}
__device__ __forceinline__ void mma_1688(float c[4],
                                         const uint32_t a[4],
                                         uint32_t b0, uint32_t b1) {
    asm volatile("mma.sync.aligned.m16n8k8.row.col.f32.tf32.tf32.f32 "
                 "{%0,%1,%2,%3}, {%4,%5,%6,%7}, {%8,%9}, {%0,%1,%2,%3};"
                 : "+f"(c[0]), "+f"(c[1]), "+f"(c[2]), "+f"(c[3])
                 : "r"(a[0]), "r"(a[1]), "r"(a[2]), "r"(a[3]), "r"(b0), "r"(b1));
}
__device__ __forceinline__ float lrelu_m(float x, float a1, float a001) {
    return x * ((x >= 0.f) ? a1 : a001);
}
__device__ __forceinline__ void cp16(uint32_t smem_addr, const void* gptr) {
    asm volatile("cp.async.cg.shared.global [%0], [%1], 16;"
                 :: "r"(smem_addr), "l"(gptr));
}

#define ESTRIDE 36    // bank = 4g + t  -> conflict-free A-frag loads
#define PSTRIDE 268   // float2 stride; bank-pair = (12t+g) mod 16 -> conflict-free

// Dynamic smem layout (bytes)
#define OFF_E0   0u          // half-tile buf0: 128*36*4 = 18432
#define OFF_E1   18432u      // half-tile buf1: 18432
#define OFF_PSB  36864u      // psb2 float2[32][268] = 68608
#define OFF_RED  105472u     // 8*64 f32 = 2048
#define OFF_AGG  107520u     // 64 f32 = 256
#define SMEM_DYN 107776u     // -> 2 CTAs/SM

// ---------------------------------------------------------------------------
// Kernel B: batch-locked persistent CTAs; psb packed float2 in smem (pad-268,
// conflict-free LDS.64 reads); B-fragments register-resident; warp-private
// cp.async E pipeline at half-receiver granularity (no CTA barrier in the
// half loop).
// ---------------------------------------------------------------------------
__global__ void __launch_bounds__(256, 2) edge_kernel(
    const float* __restrict__ edge_attr,
    const float* __restrict__ adj,
    const float* __restrict__ W_e,
    const float* __restrict__ W_n,
    float* __restrict__ out) {

    extern __shared__ __align__(16) unsigned char dynsm[];
    float2* psb2 = (float2*)(dynsm + OFF_PSB);
    float*  red  = (float*) (dynsm + OFF_RED);
    float*  agg  = (float*) (dynsm + OFF_AGG);
    const uint32_t esm0 = (uint32_t)__cvta_generic_to_shared(dynsm);

    const int tid  = threadIdx.x;
    const int bx   = blockIdx.x;
    const int wid  = tid >> 5;             // 0..7
    const int lane = tid & 31;
    const int g    = lane >> 2;            // 0..7
    const int t    = lane & 3;             // 0..3

    const int batch = bx / CPB;
    const int cb    = bx % CPB;
    const int rs    = (cb * N_) / CPB;
    const int re    = ((cb + 1) * N_) / CPB;
    const int nr    = re - rs;             // 6 or 7
    const int bn0   = batch * N_ + rs;

    // warp-private E row mapping: lane l loads rows 16w + (l>>3) + 4i, chunk l&7
    const int erow = 16*wid + (lane >> 3);
    const int eq   = lane & 7;

    // --- fire first half-load (receiver bn0, half 0) into buf0 ---
    {
        const float* esrc = edge_attr + (size_t)bn0 * (N_*DE);
        #pragma unroll
        for (int i = 0; i < 4; i++) {
            int r = erow + 4*i;
            cp16(esm0 + (uint32_t)(r*ESTRIDE + eq*4)*4u, esrc + r*DE + eq*4);
        }
        asm volatile("cp.async.commit_group;");
    }

    // --- B-fragments register-resident (one-time gmem loads, L2-shared) ---
    uint32_t bfr[8][4][2];
    #pragma unroll
    for (int nt = 0; nt < 8; nt++)
        #pragma unroll
        for (int ks = 0; ks < 4; ks++) {
            bfr[nt][ks][0] = tf32r(__ldg(W_e + (8*ks + t    )*DC + 8*nt + g));
            bfr[nt][ks][1] = tf32r(__ldg(W_e + (8*ks + t + 4)*DC + 8*nt + g));
        }

    // --- stage psb2 for this batch (once): cp = lane, s = 8i + wid ---
    {
        const float2* psrc = (const float2*)g_psb + (size_t)batch * (N_*DC/2);
        #pragma unroll
        for (int i = 0; i < 32; i++) {
            const int s  = 8*i + wid;      // 0..255
            const int cp = lane;           // 0..31
            psb2[cp*PSTRIDE + s] = psrc[s*32 + cp];
        }
    }
    __syncthreads();                        // psb2 visible to all warps

    for (int ri = 0; ri < nr; ri++) {
        const int bn = bn0 + ri;
        const float* prp = g_pr + (size_t)bn*DC + 2*t;

        // prefetch out RMW value (used ~2K cycles later)
        float outv = (tid < DO_) ? out[(size_t)bn*DO_ + tid] : 0.f;

        float ux[8], uy[8];
        #pragma unroll
        for (int nt = 0; nt < 8; nt++) { ux[nt] = 0.f; uy[nt] = 0.f; }

        #pragma unroll
        for (int h = 0; h < 2; h++) {
            const int m = 2*ri + h;

            // --- prefetch next half (warp-private rows) ---
            if (m + 1 < 2*nr) {
                const int rn = (m + 1) >> 1, hn = (m + 1) & 1;
                const float* esrc = edge_attr
                    + (size_t)(bn0 + rn) * (N_*DE) + hn * (128*DE);
                const uint32_t eb = esm0 + (uint32_t)((m + 1) & 1) * OFF_E1;
                #pragma unroll
                for (int i = 0; i < 4; i++) {
                    int r = erow + 4*i;
                    cp16(eb + (uint32_t)(r*ESTRIDE + eq*4)*4u, esrc + r*DE + eq*4);
                }
                asm volatile("cp.async.commit_group;");
                asm volatile("cp.async.wait_group 1;" ::: "memory");
            } else {
                asm volatile("cp.async.wait_group 0;" ::: "memory");
            }
            __syncwarp();                   // intra-warp visibility; no CTA barrier

            const int sg_lo = h*128 + 16*wid + g;    // global sender of row lo
            const float a_lo = __ldg(adj + (size_t)bn*N_ + sg_lo);
            const float a_hi = __ldg(adj + (size_t)bn*N_ + sg_lo + 8);
            const float a_lo1 = 0.01f * a_lo, a_hi1 = 0.01f * a_hi;

            // --- A fragments from current half buffer (own rows only) ---
            const uint32_t* Eb = (const uint32_t*)(dynsm + (m & 1)*OFF_E1);
            const int lo = 16*wid + g, hi = lo + 8;
            uint32_t afr[4][4];
            #pragma unroll
            for (int ks = 0; ks < 4; ks++) {
                const int k0 = 8*ks + t;
                afr[ks][0] = tf32r(__uint_as_float(Eb[lo*ESTRIDE + k0    ]));
                afr[ks][1] = tf32r(__uint_as_float(Eb[hi*ESTRIDE + k0    ]));
                afr[ks][2] = tf32r(__uint_as_float(Eb[lo*ESTRIDE + k0 + 4]));
                afr[ks][3] = tf32r(__uint_as_float(Eb[hi*ESTRIDE + k0 + 4]));
            }

            #pragma unroll
            for (int nt = 0; nt < 8; nt += 2) {
                const int cpA = 4*nt + t;          // channel pair 8nt+2t
                const int cpB = cpA + 4;           // channel pair 8(nt+1)+2t
                const float2 prA = *(const float2*)(prp + 8*nt);
                const float2 prB = *(const float2*)(prp + 8*nt + 8);

                const float2 pAlo = psb2[cpA*PSTRIDE + sg_lo];
                const float2 pAhi = psb2[cpA*PSTRIDE + sg_lo + 8];
                const float2 pBlo = psb2[cpB*PSTRIDE + sg_lo];
                const float2 pBhi = psb2[cpB*PSTRIDE + sg_lo + 8];

                float acc0[4] = { pAlo.x + prA.x, pAlo.y + prA.y,
                                  pAhi.x + prA.x, pAhi.y + prA.y };
                float acc1[4] = { pBlo.x + prB.x, pBlo.y + prB.y,
                                  pBhi.x + prB.x, pBhi.y + prB.y };

                #pragma unroll
                for (int ks = 0; ks < 4; ks++) {
                    mma_1688(acc0, afr[ks], bfr[nt    ][ks][0], bfr[nt    ][ks][1]);
                    mma_1688(acc1, afr[ks], bfr[nt + 1][ks][0], bfr[nt + 1][ks][1]);
                }

                ux[nt]   += lrelu_m(acc0[0], a_lo, a_lo1) + lrelu_m(acc0[2], a_hi, a_hi1);
                uy[nt]   += lrelu_m(acc0[1], a_lo, a_lo1) + lrelu_m(acc0[3], a_hi, a_hi1);
                ux[nt+1] += lrelu_m(acc1[0], a_lo, a_lo1) + lrelu_m(acc1[2], a_hi, a_hi1);
                uy[nt+1] += lrelu_m(acc1[1], a_lo, a_lo1) + lrelu_m(acc1[3], a_hi, a_hi1);
            }
        } // halves

        // --- cross-lane butterfly over the 8 groups ---
        #pragma unroll
        for (int nt = 0; nt < 8; nt++) {
            #pragma unroll
            for (int st = 4; st <= 16; st <<= 1) {
                ux[nt] += __shfl_xor_sync(0xffffffffu, ux[nt], st);
                uy[nt] += __shfl_xor_sync(0xffffffffu, uy[nt], st);
            }
        }
        if (lane < 4) {
            #pragma unroll
            for (int nt = 0; nt < 8; nt++)
                *(float2*)&red[wid*DC + 8*nt + 2*t] = make_float2(ux[nt], uy[nt]);
        }
        __syncthreads();

        if (tid < DC) {
            float a = 0.f;
            #pragma unroll
            for (int w = 0; w < 8; w++) a += red[w*DC + tid];
            agg[tid] = a;
        }
        __syncthreads();

        if (tid < DO_) {
            float sum = outv;
            #pragma unroll 8
            for (int cc = 0; cc < DC; cc++)
                sum = fmaf(agg[cc], W_n[(DN + cc)*DO_ + tid], sum);
            out[(size_t)bn*DO_ + tid] = sum;
        }
    } // receivers
}

// ---------------------------------------------------------------------------
extern "C" void kernel_launch(void* const* d_in, const int* in_sizes, int n_in,
                              void* d_out, int out_size) {
    const float* node = (const float*)d_in[0];
    const float* edge = (const float*)d_in[1];
    const float* adjp = (const float*)d_in[2];
    const float* W_e  = (const float*)d_in[3];
    const float* b_e  = (const float*)d_in[4];
    const float* W_n  = (const float*)d_in[5];
    const float* b_n  = (const float*)d_in[6];
    float* out = (float*)d_out;

    cudaFuncSetAttribute(edge_kernel, cudaFuncAttributeMaxDynamicSharedMemorySize, SMEM_DYN);

    precompute_kernel<<<B_*N_, 64>>>(node, W_e, b_e, W_n, b_n, out);
    edge_kernel<<<GRID, 256, SMEM_DYN>>>(edge, adjp, W_e, W_n, out);
}